// round 1
// baseline (speedup 1.0000x reference)
#include <cuda_runtime.h>
#include <math.h>
#include <stdint.h>

#define NB 16
#define NA 25200
#define NC 80
#define KPRE 256
#define MAXB 100
#define CAP 2048
#define NBINS 2048
#define SCORE_THR 0.25f
#define IOU_THR 0.1f

// layer layout: p5 (20x20) anchors [0,1200), p4 (40x40) [1200,6000), p3 (80x80) [6000,25200)

__device__ float4 g_boxes[NB * NA];                       // corner boxes
__device__ float g_scores[(size_t)NB * NC * NA];          // class-major scores (or -1)
__device__ unsigned long long g_keys[NB * NC * KPRE];     // kept keys per (b, class, slot)

__constant__ float c_anch[9][2] = {
    {116.f, 90.f}, {156.f, 198.f}, {373.f, 326.f},   // p5 -> ANCHORS[6:9]
    {30.f, 61.f},  {62.f, 45.f},   {59.f, 119.f},    // p4 -> ANCHORS[3:6]
    {10.f, 13.f},  {16.f, 30.f},   {33.f, 23.f}      // p3 -> ANCHORS[0:3]
};

// ---------------------------------------------------------------------------
// Pass 1: decode + threshold + transpose scores to class-major
// ---------------------------------------------------------------------------
__global__ __launch_bounds__(256) void decode_kernel(
    const float* __restrict__ p5, const float* __restrict__ p4, const float* __restrict__ p3)
{
    int t = blockIdx.x * blockDim.x + threadIdx.x;
    if (t >= NB * NA) return;
    int b = t / NA;
    int gi = t - b * NA;

    int layer, base, g;
    const float* fm;
    float ratio;
    if (gi < 1200)      { layer = 0; base = 0;    g = 20; fm = p5; ratio = 32.f; }
    else if (gi < 6000) { layer = 1; base = 1200; g = 40; fm = p4; ratio = 16.f; }
    else                { layer = 2; base = 6000; g = 80; fm = p3; ratio = 8.f;  }

    int li = gi - base;
    int cell = li / 3;
    int a = li - cell * 3;
    int xi = cell % g;
    int yi = cell / g;
    const float* v = fm + ((size_t)(b * g + yi) * g + xi) * 255 + a * 85;

    float t0 = v[0], t1 = v[1], t2 = v[2], t3 = v[3], t4 = v[4];
    float sx = 1.f / (1.f + expf(-t0));
    float sy = 1.f / (1.f + expf(-t1));
    float cx = (sx + (float)xi) * ratio;
    float cy = (sy + (float)yi) * ratio;
    float w = expf(t2) * c_anch[layer * 3 + a][0];
    float h = expf(t3) * c_anch[layer * 3 + a][1];
    float conf = 1.f / (1.f + expf(-t4));

    float4 box = make_float4(cx - w * 0.5f, cy - h * 0.5f, cx + w * 0.5f, cy + h * 0.5f);
    g_boxes[b * NA + gi] = box;

    // logit-space screen for score > 0.25 (conservative margin, exact recheck below)
    float thr;
    if (conf > SCORE_THR) {
        float q = SCORE_THR / conf;      // < 1
        thr = logf(q / (1.f - q)) - 1e-3f;
    } else {
        thr = __int_as_float(0x7F800000); // +inf: no class can pass
    }

    float* srow = g_scores + (size_t)b * NC * NA + gi;
#pragma unroll
    for (int c = 0; c < NC; c++) {
        float xc = v[5 + c];
        float s = -1.f;
        if (xc > thr) {
            float sc = conf * (1.f / (1.f + expf(-xc)));
            if (sc > SCORE_THR) s = sc;   // exact JAX-equivalent threshold decision
        }
        srow[(size_t)c * NA] = s;         // coalesced across warp for each c
    }
}

// ---------------------------------------------------------------------------
// Pass 2: per-(image,class) exact top-256 (histogram pivot + bitonic) + NMS
// ---------------------------------------------------------------------------
__global__ __launch_bounds__(256) void nms_kernel()
{
    __shared__ unsigned int hist[NBINS];
    __shared__ unsigned long long buf[CAP];
    __shared__ int sscan[256];
    __shared__ unsigned int cnt;
    __shared__ int pivot;
    __shared__ float bx1[KPRE], by1[KPRE], bx2[KPRE], by2[KPRE], barea[KPRE], bscore[KPRE];
    __shared__ int banch[KPRE];
    __shared__ int supp[KPRE];

    int bc = blockIdx.x;
    int b = bc / NC;
    int c = bc - b * NC;
    const float* S = g_scores + ((size_t)b * NC + c) * NA;
    int tid = threadIdx.x;

    for (int i = tid; i < NBINS; i += 256) hist[i] = 0;
    if (tid == 0) { cnt = 0; pivot = 0; }
    __syncthreads();

    // histogram of score float bits over (0.25, 1.0): bits in (0x3E800000, 0x3F800000)
    for (int a = tid; a < NA; a += 256) {
        float s = S[a];
        if (s > 0.f) {
            unsigned bits = __float_as_uint(s);
            unsigned bin = (bits - 0x3E800000u) >> 13;
            if (bin > 2047u) bin = 2047u;
            atomicAdd(&hist[bin], 1u);
        }
    }
    __syncthreads();

    // pivot: thread tid covers descending ranks [8*tid, 8*tid+8), bin = 2047 - rank
    int lc[8];
    int local = 0;
#pragma unroll
    for (int k = 0; k < 8; k++) { lc[k] = (int)hist[2047 - (tid * 8 + k)]; local += lc[k]; }
    sscan[tid] = local;
    __syncthreads();
    for (int off = 1; off < 256; off <<= 1) {
        int vv = sscan[tid];
        int u = (tid >= off) ? sscan[tid - off] : 0;
        __syncthreads();
        sscan[tid] = vv + u;
        __syncthreads();
    }
    int incl = sscan[tid];
    int excl = incl - local;
    if (excl < KPRE && incl >= KPRE) {
        int run = excl;
#pragma unroll
        for (int k = 0; k < 8; k++) {
            run += lc[k];
            if (run >= KPRE) { pivot = 2047 - (tid * 8 + k); break; }
        }
    }
    __syncthreads();
    int P = pivot;

    // collect candidates with bin >= P as (scorebits << 32) | ~anchor  (lower idx wins ties)
    for (int a = tid; a < NA; a += 256) {
        float s = S[a];
        if (s > 0.f) {
            unsigned bits = __float_as_uint(s);
            unsigned bin = (bits - 0x3E800000u) >> 13;
            if (bin > 2047u) bin = 2047u;
            if ((int)bin >= P) {
                unsigned pos = atomicAdd(&cnt, 1u);
                if (pos < CAP)
                    buf[pos] = ((unsigned long long)bits << 32) | (unsigned)(0xFFFFFFFFu - (unsigned)a);
            }
        }
    }
    __syncthreads();
    int n = cnt < CAP ? (int)cnt : CAP;
    for (int i = tid; i < CAP; i += 256)
        if (i >= n) buf[i] = 0ULL;
    __syncthreads();

    // bitonic sort, descending
    for (int k = 2; k <= CAP; k <<= 1) {
        for (int j = k >> 1; j > 0; j >>= 1) {
            for (int i = tid; i < CAP; i += 256) {
                int ixj = i ^ j;
                if (ixj > i) {
                    unsigned long long A = buf[i], Bv = buf[ixj];
                    bool desc = ((i & k) == 0);
                    if (desc ? (A < Bv) : (A > Bv)) { buf[i] = Bv; buf[ixj] = A; }
                }
            }
            __syncthreads();
        }
    }

    // load top-256 into smem box arrays
    unsigned long long key = buf[tid];
    bool valid = key != 0ULL;
    float sc;
    int a;
    if (valid) {
        sc = __uint_as_float((unsigned)(key >> 32));
        a = (int)(0xFFFFFFFFu - (unsigned)(key & 0xFFFFFFFFu));
    } else {
        sc = -1.f;
        a = 0;
    }
    float4 bb = valid ? g_boxes[b * NA + a] : make_float4(0.f, 0.f, 0.f, 0.f);
    bx1[tid] = bb.x; by1[tid] = bb.y; bx2[tid] = bb.z; by2[tid] = bb.w;
    float area = fmaxf(bb.z - bb.x, 0.f) * fmaxf(bb.w - bb.y, 0.f);   // from rounded corners, like ref
    barea[tid] = area;
    bscore[tid] = sc;
    banch[tid] = a;
    supp[tid] = valid ? 0 : 1;
    __syncthreads();

    float mx1 = bb.x, my1 = bb.y, mx2 = bb.z, my2 = bb.w, ma = area;
    bool msupp = !valid;
    for (int i = 0; i < KPRE - 1; i++) {
        if (!supp[i] && tid > i && !msupp) {
            float iw = fminf(mx2, bx2[i]) - fmaxf(mx1, bx1[i]);
            float ih = fminf(my2, by2[i]) - fmaxf(my1, by1[i]);
            iw = fmaxf(iw, 0.f);
            ih = fmaxf(ih, 0.f);
            float inter = iw * ih;
            float uni = ma + barea[i] - inter;
            float iou = inter / fmaxf(uni, 1e-9f);   // match ref formula exactly
            if (iou > IOU_THR) { msupp = true; supp[tid] = 1; }
        }
        __syncthreads();
    }

    // keep + cumsum cap at MAXB
    int keep = msupp ? 0 : 1;
    sscan[tid] = keep;
    __syncthreads();
    for (int off = 1; off < 256; off <<= 1) {
        int vv = sscan[tid];
        int u = (tid >= off) ? sscan[tid - off] : 0;
        __syncthreads();
        sscan[tid] = vv + u;
        __syncthreads();
    }
    int rank = sscan[tid];
    keep = keep && (rank <= MAXB);

    unsigned long long outkey = 0ULL;
    if (keep) {
        int flatpos = c * KPRE + tid;
        unsigned low = ((unsigned)(20479 - flatpos) << 15) | (unsigned)banch[tid];
        outkey = ((unsigned long long)__float_as_uint(bscore[tid]) << 32) | low;
    }
    g_keys[(size_t)b * NC * KPRE + c * KPRE + tid] = outkey;
}

// ---------------------------------------------------------------------------
// Pass 3: per-image top-100 over kept keys + gather output
// ---------------------------------------------------------------------------
__global__ __launch_bounds__(256) void final_kernel(float* __restrict__ out)
{
    __shared__ unsigned int hist[NBINS];
    __shared__ unsigned long long buf[CAP];
    __shared__ int sscan[256];
    __shared__ unsigned int cnt;
    __shared__ int pivot;

    int b = blockIdx.x;
    int tid = threadIdx.x;
    const unsigned long long* K = g_keys + (size_t)b * NC * KPRE;

    for (int i = tid; i < NBINS; i += 256) hist[i] = 0;
    if (tid == 0) { cnt = 0; pivot = 0; }
    __syncthreads();

    for (int i = tid; i < NC * KPRE; i += 256) {
        unsigned long long k = K[i];
        if (k) {
            unsigned bits = (unsigned)(k >> 32);
            unsigned bin = (bits - 0x3E800000u) >> 13;
            if (bin > 2047u) bin = 2047u;
            atomicAdd(&hist[bin], 1u);
        }
    }
    __syncthreads();

    int lc[8];
    int local = 0;
#pragma unroll
    for (int kk = 0; kk < 8; kk++) { lc[kk] = (int)hist[2047 - (tid * 8 + kk)]; local += lc[kk]; }
    sscan[tid] = local;
    __syncthreads();
    for (int off = 1; off < 256; off <<= 1) {
        int vv = sscan[tid];
        int u = (tid >= off) ? sscan[tid - off] : 0;
        __syncthreads();
        sscan[tid] = vv + u;
        __syncthreads();
    }
    int incl = sscan[tid];
    int excl = incl - local;
    if (excl < MAXB && incl >= MAXB) {
        int run = excl;
#pragma unroll
        for (int kk = 0; kk < 8; kk++) {
            run += lc[kk];
            if (run >= MAXB) { pivot = 2047 - (tid * 8 + kk); break; }
        }
    }
    __syncthreads();
    int P = pivot;

    for (int i = tid; i < NC * KPRE; i += 256) {
        unsigned long long k = K[i];
        if (k) {
            unsigned bits = (unsigned)(k >> 32);
            unsigned bin = (bits - 0x3E800000u) >> 13;
            if (bin > 2047u) bin = 2047u;
            if ((int)bin >= P) {
                unsigned pos = atomicAdd(&cnt, 1u);
                if (pos < CAP) buf[pos] = k;
            }
        }
    }
    __syncthreads();
    int n = cnt < CAP ? (int)cnt : CAP;
    for (int i = tid; i < CAP; i += 256)
        if (i >= n) buf[i] = 0ULL;
    __syncthreads();

    for (int k2 = 2; k2 <= CAP; k2 <<= 1) {
        for (int j = k2 >> 1; j > 0; j >>= 1) {
            for (int i = tid; i < CAP; i += 256) {
                int ixj = i ^ j;
                if (ixj > i) {
                    unsigned long long A = buf[i], Bv = buf[ixj];
                    bool desc = ((i & k2) == 0);
                    if (desc ? (A < Bv) : (A > Bv)) { buf[i] = Bv; buf[ixj] = A; }
                }
            }
            __syncthreads();
        }
    }

    if (tid < MAXB) {
        unsigned long long k = buf[tid];
        float x1 = -1.f, y1 = -1.f, x2 = -1.f, y2 = -1.f, scv = -1.f, lab = -1.f;
        if (k) {
            unsigned bits = (unsigned)(k >> 32);
            scv = __uint_as_float(bits);
            unsigned low = (unsigned)(k & 0xFFFFFFFFu);
            int flatpos = 20479 - (int)(low >> 15);
            int a = (int)(low & 0x7FFFu);
            int cls = flatpos >> 8;   // / KPRE
            float4 bb = g_boxes[b * NA + a];
            x1 = bb.x; y1 = bb.y; x2 = bb.z; y2 = bb.w;
            lab = (float)cls;
        }
        float* ob = out;                        // [NB][MAXB][4]
        float* os = out + NB * MAXB * 4;        // [NB][MAXB]
        float* ol = out + NB * MAXB * 5;        // [NB][MAXB]
        int r = tid;
        ob[(b * MAXB + r) * 4 + 0] = x1;
        ob[(b * MAXB + r) * 4 + 1] = y1;
        ob[(b * MAXB + r) * 4 + 2] = x2;
        ob[(b * MAXB + r) * 4 + 3] = y2;
        os[b * MAXB + r] = scv;
        ol[b * MAXB + r] = lab;
    }
}

// ---------------------------------------------------------------------------
extern "C" void kernel_launch(void* const* d_in, const int* in_sizes, int n_in,
                              void* d_out, int out_size)
{
    const float* p5 = (const float*)d_in[0];
    const float* p4 = (const float*)d_in[1];
    const float* p3 = (const float*)d_in[2];
    float* out = (float*)d_out;

    decode_kernel<<<(NB * NA + 255) / 256, 256>>>(p5, p4, p3);
    nms_kernel<<<NB * NC, 256>>>();
    final_kernel<<<NB, 256>>>(out);
}